// round 4
// baseline (speedup 1.0000x reference)
#include <cuda_runtime.h>

typedef unsigned long long ull;

#define BN 8
#define NPT 256
#define FF 32
#define NRBF_ 50
#define HH 128
#define NM1 255
#define NCOL 512
#define EPSV 1e-6f
#define STRIDE_B (NPT*3 + NPT*FF)   /* 8960 */
#define NCTA 152
#define NT 512
#define NW 16

__device__ float g_vxf[BN*NPT*3];
__device__ float g_tr[BN*NPT];
__device__ int   g_done = 0;

struct SmemLayout {
    float  Wc[NRBF_*NCOL];   // [k][512]: s1W1 | s2W1 | fW1 | mu*s1W1  (102400 B)
    float2 A2[NRBF_*64];     // rbf broadcast-packed [k][pair]          (25600 B)
    float  Wsum[3][FF*HH];   // feats->hidden summed weights            (49152 B)
    float  fW2s[HH*FF];      // second layer of f-net                   (16384 B)
    float  bsum[3][HH];
    float  fb2s[FF];
    float  xs[NPT*3];
    float  ms[NRBF_ + 2];
    float  pd[64];
    float  pr[64*3];
    float  feats_s[FF];
    float  smax[FF];
    float  cvec[3][HH];
    float  accst[NW][HH];
    float  wpart[NW][8];
    float  fin[BN*4];
    float  lastflag;
};

__device__ __forceinline__ float2 unpack2(ull v) {
    float2 r; asm("mov.b64 {%0, %1}, %2;" : "=f"(r.x), "=f"(r.y) : "l"(v)); return r;
}
__device__ __forceinline__ void ffma2(ull &d, ull a, ull b) {
    asm("fma.rn.f32x2 %0, %1, %2, %3;" : "=l"(d) : "l"(a), "l"(b), "l"(d));
}

__global__ __launch_bounds__(NT, 1) void k_main(
    const float* __restrict__ state,
    const float* __restrict__ mus,
    const float* __restrict__ gammap,
    const float* __restrict__ s1W1, const float* __restrict__ s1b1,
    const float* __restrict__ s1W2, const float* __restrict__ s1b2,
    const float* __restrict__ s2W1, const float* __restrict__ s2b1,
    const float* __restrict__ s2W2, const float* __restrict__ s2b2,
    const float* __restrict__ fW1,  const float* __restrict__ fb1,
    const float* __restrict__ fW2,  const float* __restrict__ fb2,
    float* __restrict__ out)
{
    extern __shared__ char smraw[];
    SmemLayout& S = *reinterpret_cast<SmemLayout*>(smraw);
    const int tid = threadIdx.x;
    const int tx  = tid & 31;
    const int ty  = tid >> 5;
    const float gamma = gammap[0];
    const float n2g   = -2.0f * gamma;
    const float b2s1  = s1b2[0];
    const float b2s2  = s2b2[0];

    // ---- One-time per-CTA weight staging ----
    for (int e = tid; e < NRBF_*HH; e += NT) {
        int k = e >> 7, h = e & 127;
        float w1 = s1W1[e];
        S.Wc[k*NCOL + h]       = w1;
        S.Wc[k*NCOL + 128 + h] = s2W1[e];
        S.Wc[k*NCOL + 256 + h] = fW1[e];
        S.Wc[k*NCOL + 384 + h] = mus[k] * w1;
    }
    for (int e = tid; e < FF*HH; e += NT) {
        S.Wsum[0][e] = s1W1[NRBF_*HH + e] + s1W1[(NRBF_+FF)*HH + e];
        S.Wsum[1][e] = s2W1[NRBF_*HH + e] + s2W1[(NRBF_+FF)*HH + e];
        S.Wsum[2][e] = fW1[NRBF_*HH + e];
    }
    for (int e = tid; e < HH*FF; e += NT) S.fW2s[e] = fW2[e];
    if (tid < HH) {
        S.bsum[0][tid] = s1b1[tid];
        S.bsum[1][tid] = s2b1[tid];
        S.bsum[2][tid] = fb1[tid];
    }
    if (tid < FF)    S.fb2s[tid] = fb2[tid];
    if (tid < NRBF_) S.ms[tid]   = mus[tid];

    float w2s1v[4], w2s2v[4];
    #pragma unroll
    for (int q = 0; q < 4; q++) {
        w2s1v[q] = s1W2[tx*4 + q];
        w2s2v[q] = s2W2[tx*4 + q];
    }

    for (int bi = blockIdx.x; bi < BN*NPT; bi += gridDim.x) {
        const int b = bi >> 8;
        const int i = bi & 255;
        const float* st = state + b*STRIDE_B;
        __syncthreads();   // also covers weight staging on first iter
        for (int e = tid; e < NPT*3; e += NT) S.xs[e] = st[e];
        if (tid < FF) S.feats_s[tid] = st[NPT*3 + i*FF + tid];
        __syncthreads();

        if (ty == 0) {  // softmax(feats_i) over F=32 by warp 0
            float v = S.feats_s[tx];
            float m = v;
            #pragma unroll
            for (int o = 16; o; o >>= 1) m = fmaxf(m, __shfl_xor_sync(0xffffffffu, m, o));
            float e = __expf(v - m);
            float s = e;
            #pragma unroll
            for (int o = 16; o; o >>= 1) s += __shfl_xor_sync(0xffffffffu, s, o);
            S.smax[tx] = e / s;
        }
        __syncthreads();

        // Per-(b,i) constant part of hidden pre-activations (3 nets x 128 h)
        if (tid < 3*HH) {
            int net = tid >> 7, h = tid & 127;
            const float* wv = (net < 2) ? S.feats_s : S.smax;
            const float* Wn = S.Wsum[net];
            float c = S.bsum[net][h];
            #pragma unroll
            for (int f = 0; f < FF; f++) c += wv[f] * Wn[f*HH + h];
            S.cvec[net][h] = c;
        }
        __syncthreads();

        float c1[4], c2[4], cf[4];
        #pragma unroll
        for (int q = 0; q < 4; q++) {
            c1[q] = S.cvec[0][tx*4 + q];
            c2[q] = S.cvec[1][tx*4 + q];
            cf[q] = S.cvec[2][tx*4 + q];
        }
        const float xi0 = S.xs[i*3+0], xi1 = S.xs[i*3+1], xi2 = S.xs[i*3+2];

        float accf0=0.f, accf1=0.f, accf2=0.f, accf3=0.f;
        float vx0=0.f, vy0=0.f, vz0=0.f;
        float wxa=0.f, wya=0.f, wza=0.f;
        float trc=0.f;

        for (int tile = 0; tile < 4; tile++) {
            if (tid < 64) {
                int gp = tile*64 + tid;
                float r0 = 0.f, r1 = 0.f, r2 = 0.f;
                if (gp < NM1) {
                    int j = (gp < i) ? gp : gp + 1;
                    r0 = xi0 - S.xs[j*3+0];
                    r1 = xi1 - S.xs[j*3+1];
                    r2 = xi2 - S.xs[j*3+2];
                }
                S.pd[tid] = sqrtf(r0*r0 + r1*r1 + r2*r2 + EPSV);
                S.pr[tid*3+0] = r0; S.pr[tid*3+1] = r1; S.pr[tid*3+2] = r2;
            }
            __syncthreads();
            for (int e = tid; e < NRBF_*64; e += NT) {
                int k = e >> 6, p = e & 63;
                float t = S.pd[p] - S.ms[k];
                float v = __expf(-gamma * t * t);
                S.A2[e] = make_float2(v, v);
            }
            __syncthreads();

            // GEMM: [64 x 50] @ [50 x 512] with f32x2 packed FMA
            // warp ty owns pair rows ty*4 .. ty*4+3
            ull acc[4][4][2];
            #pragma unroll
            for (int j = 0; j < 4; j++)
                #pragma unroll
                for (int p = 0; p < 4; p++) { acc[j][p][0] = 0ull; acc[j][p][1] = 0ull; }

            const ull* Arow = reinterpret_cast<const ull*>(S.A2) + ty*4;
            const ull* Wu   = reinterpret_cast<const ull*>(S.Wc) + tx*2;
            #pragma unroll 5
            for (int k = 0; k < NRBF_; k++) {
                ull av[4];
                #pragma unroll
                for (int p = 0; p < 4; p++) av[p] = Arow[k*64 + p];
                #pragma unroll
                for (int j = 0; j < 4; j++) {
                    ulonglong2 bv = *reinterpret_cast<const ulonglong2*>(Wu + k*256 + j*64);
                    #pragma unroll
                    for (int p = 0; p < 4; p++) {
                        ffma2(acc[j][p][0], bv.x, av[p]);
                        ffma2(acc[j][p][1], bv.y, av[p]);
                    }
                }
            }

            // Epilogue: silu / s1 / s2 / exact d-gradient, warp reductions
            #pragma unroll
            for (int p = 0; p < 4; p++) {
                int lp = ty*4 + p;
                int gp = tile*64 + lp;
                float d  = S.pd[lp];
                float r0 = S.pr[lp*3+0], r1 = S.pr[lp*3+1], r2 = S.pr[lp*3+2];
                float s1part = 0.f, s2part = 0.f, gpart = 0.f;
                float afq[4];
                #pragma unroll
                for (int half = 0; half < 2; half++) {
                    float2 v1 = unpack2(acc[0][p][half]);
                    float2 v2 = unpack2(acc[1][p][half]);
                    float2 vf = unpack2(acc[2][p][half]);
                    float2 vp = unpack2(acc[3][p][half]);
                    #pragma unroll
                    for (int sub = 0; sub < 2; sub++) {
                        int q = half*2 + sub;
                        float phi1 = sub ? v1.y : v1.x;
                        float phi2 = sub ? v2.y : v2.x;
                        float phif = sub ? vf.y : vf.x;
                        float psi  = sub ? vp.y : vp.x;
                        float pre1 = phi1 + c1[q];
                        float sig1 = __fdividef(1.f, 1.f + __expf(-pre1));
                        s1part += pre1 * sig1 * w2s1v[q];
                        float dsil = sig1 * (1.f + pre1 * (1.f - sig1));
                        float tq = n2g * (d * phi1 - psi);
                        gpart += w2s1v[q] * dsil * tq;
                        float pre2 = phi2 + c2[q];
                        float sig2 = __fdividef(1.f, 1.f + __expf(-pre2));
                        s2part += pre2 * sig2 * w2s2v[q];
                        float pref = phif + cf[q];
                        float sigf = __fdividef(1.f, 1.f + __expf(-pref));
                        afq[q] = pref * sigf;
                    }
                }
                #pragma unroll
                for (int o = 16; o; o >>= 1) {
                    s1part += __shfl_xor_sync(0xffffffffu, s1part, o);
                    s2part += __shfl_xor_sync(0xffffffffu, s2part, o);
                    gpart  += __shfl_xor_sync(0xffffffffu, gpart,  o);
                }
                if (gp < NM1) {
                    float s1 = s1part + b2s1;
                    float s2 = s2part + b2s2;
                    float r2d = __fdividef(d*d - EPSV, d);   // |r|^2 / d
                    vx0 += r0*s1; vy0 += r1*s1; vz0 += r2*s1;
                    wxa += r0*s2; wya += r1*s2; wza += r2*s2;
                    trc += r2d * gpart + 3.f * s1;
                    accf0 += afq[0]; accf1 += afq[1]; accf2 += afq[2]; accf3 += afq[3];
                }
            }
            __syncthreads();
        } // tiles

        // Combine per-warp partials
        S.accst[ty][tx*4+0] = accf0;
        S.accst[ty][tx*4+1] = accf1;
        S.accst[ty][tx*4+2] = accf2;
        S.accst[ty][tx*4+3] = accf3;
        if (tx == 0) {
            S.wpart[ty][0] = vx0; S.wpart[ty][1] = vy0; S.wpart[ty][2] = vz0;
            S.wpart[ty][3] = wxa; S.wpart[ty][4] = wya; S.wpart[ty][5] = wza;
            S.wpart[ty][6] = trc;
        }
        __syncthreads();
        if (tid < HH) {
            float t = 0.f;
            #pragma unroll
            for (int w = 0; w < NW; w++) t += S.accst[w][tid];
            S.accst[0][tid] = t;
        }
        __syncthreads();
        if (tid < FF) {
            float s = 0.f;
            for (int h = 0; h < HH; h++) s += S.accst[0][h] * S.fW2s[h*FF + tid];
            out[b*STRIDE_B + NPT*3 + i*FF + tid] = S.fb2s[tid] + s * (1.f/255.f);
        }
        if (tid == 0) {
            float v0=0,v1=0,v2=0,w0=0,w1=0,w2=0,tr=0;
            #pragma unroll
            for (int w = 0; w < NW; w++) {
                v0 += S.wpart[w][0]; v1 += S.wpart[w][1]; v2 += S.wpart[w][2];
                w0 += S.wpart[w][3]; w1 += S.wpart[w][4]; w2 += S.wpart[w][5];
                tr += S.wpart[w][6];
            }
            const float inv = 1.f/255.f;
            v0 *= inv; v1 *= inv; v2 *= inv;
            w0 *= inv; w1 *= inv; w2 *= inv;
            // v_x = vx0 + cross(w, vx0)   (linearity of the Levi-Civita term)
            float fx = v0 + (w1*v2 - w2*v1);
            float fy = v1 + (w2*v0 - w0*v2);
            float fz = v2 + (w0*v1 - w1*v0);
            g_vxf[bi*3+0] = fx; g_vxf[bi*3+1] = fy; g_vxf[bi*3+2] = fz;
            g_tr[bi] = tr * inv;
        }
    }

    // ---- Last-block finalization: mean removal + trace ----
    __syncthreads();
    if (tid == 0) {
        __threadfence();
        int v = atomicAdd(&g_done, 1);
        S.lastflag = (v == (int)gridDim.x - 1) ? 1.f : 0.f;
    }
    __syncthreads();
    if (S.lastflag != 0.f) {
        __threadfence();
        // warps 0..7: warp ty sums batch b = ty
        if (ty < BN) {
            float s0 = 0.f, s1 = 0.f, s2 = 0.f, st = 0.f;
            for (int ii = tx; ii < NPT; ii += 32) {
                int e = ty*NPT + ii;
                s0 += g_vxf[e*3+0]; s1 += g_vxf[e*3+1]; s2 += g_vxf[e*3+2];
                st += g_tr[e];
            }
            #pragma unroll
            for (int o = 16; o; o >>= 1) {
                s0 += __shfl_xor_sync(0xffffffffu, s0, o);
                s1 += __shfl_xor_sync(0xffffffffu, s1, o);
                s2 += __shfl_xor_sync(0xffffffffu, s2, o);
                st += __shfl_xor_sync(0xffffffffu, st, o);
            }
            if (tx == 0) {
                S.fin[ty*4+0] = s0 * (1.f/NPT);
                S.fin[ty*4+1] = s1 * (1.f/NPT);
                S.fin[ty*4+2] = s2 * (1.f/NPT);
                S.fin[ty*4+3] = st;
            }
        }
        __syncthreads();
        for (int e = tid; e < BN*NPT; e += NT) {
            int bb = e >> 8, ii = e & 255;
            float m0 = S.fin[bb*4+0], m1 = S.fin[bb*4+1], m2 = S.fin[bb*4+2];
            out[bb*STRIDE_B + ii*3+0] = g_vxf[e*3+0] - m0;
            out[bb*STRIDE_B + ii*3+1] = g_vxf[e*3+1] - m1;
            out[bb*STRIDE_B + ii*3+2] = g_vxf[e*3+2] - m2;
        }
        if (tid < BN) out[BN*STRIDE_B + tid] = S.fin[tid*4+3];
        if (tid == 0) g_done = 0;   // self-reset for next launch
    }
}

extern "C" void kernel_launch(void* const* d_in, const int* in_sizes, int n_in,
                              void* d_out, int out_size) {
    (void)in_sizes; (void)n_in; (void)out_size;
    const float* state = (const float*)d_in[1];
    const float* mus   = (const float*)d_in[2];
    const float* gamma = (const float*)d_in[3];
    const float* s1W1  = (const float*)d_in[4];
    const float* s1b1  = (const float*)d_in[5];
    const float* s1W2  = (const float*)d_in[6];
    const float* s1b2  = (const float*)d_in[7];
    const float* s2W1  = (const float*)d_in[8];
    const float* s2b1  = (const float*)d_in[9];
    const float* s2W2  = (const float*)d_in[10];
    const float* s2b2  = (const float*)d_in[11];
    const float* fW1   = (const float*)d_in[12];
    const float* fb1   = (const float*)d_in[13];
    const float* fW2   = (const float*)d_in[14];
    const float* fb2   = (const float*)d_in[15];
    float* out = (float*)d_out;

    const size_t smem = sizeof(SmemLayout);
    cudaFuncSetAttribute(k_main, cudaFuncAttributeMaxDynamicSharedMemorySize, (int)smem);

    k_main<<<NCTA, NT, smem>>>(state, mus, gamma,
                               s1W1, s1b1, s1W2, s1b2,
                               s2W1, s2b1, s2W2, s2b2,
                               fW1, fb1, fW2, fb2, out);
}

// round 9
// speedup vs baseline: 1.0311x; 1.0311x over previous
#include <cuda_runtime.h>

typedef unsigned long long ull;

#define BN 8
#define NPT 256
#define FF 32
#define NRBF_ 50
#define NK2 25
#define HH 128
#define NM1 255
#define NCOL 512
#define EPSV 1e-6f
#define STRIDE_B (NPT*3 + NPT*FF)   /* 8960 */
#define NCTA 152
#define NT 512
#define NW 16

__device__ float g_vxf[BN*NPT*3];
__device__ float g_tr[BN*NPT];
__device__ int   g_done = 0;

// Wc column layout: [0:128)=s1W  [128:256)=mu*s1W  [256:384)=s2W  [384:512)=fW
struct SmemLayout {
    float      Wc[NRBF_*NCOL];    // 102400 B
    ulonglong2 A2q[NK2*64];       // [k2][pair]: {(a_{2k2} dup),(a_{2k2+1} dup)}  25600 B
    float      Wsum[3][FF*HH];    // 49152 B
    float      fW2s[HH*FF];       // 16384 B
    float      bsum[3][HH];
    float      fb2s[FF];
    float      xs[NPT*3];
    float      ms[NRBF_ + 2];
    float      pd[64];
    float      pr[64*3];
    float      feats_s[FF];
    float      smax[FF];
    float      cvec[3][HH];
    float      accst[8][HH];
    float      wpart[NW][8];
    float      fin[BN*4];
    float      lastflag;
};

__device__ __forceinline__ float2 unpack2(ull v) {
    float2 r; asm("mov.b64 {%0, %1}, %2;" : "=f"(r.x), "=f"(r.y) : "l"(v)); return r;
}
__device__ __forceinline__ ull pack2(float x) {
    ull r; asm("mov.b64 %0, {%1, %1};" : "=l"(r) : "f"(x)); return r;
}
__device__ __forceinline__ void ffma2(ull &d, ull a, ull b) {
    asm("fma.rn.f32x2 %0, %1, %2, %3;" : "=l"(d) : "l"(a), "l"(b), "l"(d));
}

__global__ __launch_bounds__(NT, 1) void k_main(
    const float* __restrict__ state,
    const float* __restrict__ mus,
    const float* __restrict__ gammap,
    const float* __restrict__ s1W1, const float* __restrict__ s1b1,
    const float* __restrict__ s1W2, const float* __restrict__ s1b2,
    const float* __restrict__ s2W1, const float* __restrict__ s2b1,
    const float* __restrict__ s2W2, const float* __restrict__ s2b2,
    const float* __restrict__ fW1,  const float* __restrict__ fb1,
    const float* __restrict__ fW2,  const float* __restrict__ fb2,
    float* __restrict__ out)
{
    extern __shared__ char smraw[];
    SmemLayout& S = *reinterpret_cast<SmemLayout*>(smraw);
    const int tid = threadIdx.x;
    const int tx  = tid & 31;
    const int ty  = tid >> 5;
    const int g   = ty >> 1;     // pair-group 0..7 (owns pairs g*8..g*8+7)
    const int hf  = ty & 1;      // column half: 0 -> s1|psi, 1 -> s2|f
    const float gamma = gammap[0];
    const float n2g   = -2.0f * gamma;

    // ---- One-time per-CTA weight staging ----
    for (int e = tid; e < NRBF_*HH; e += NT) {
        int k = e >> 7, h = e & 127;
        float w1 = s1W1[e];
        S.Wc[k*NCOL + h]       = w1;
        S.Wc[k*NCOL + 128 + h] = mus[k] * w1;
        S.Wc[k*NCOL + 256 + h] = s2W1[e];
        S.Wc[k*NCOL + 384 + h] = fW1[e];
    }
    for (int e = tid; e < FF*HH; e += NT) {
        S.Wsum[0][e] = s1W1[NRBF_*HH + e] + s1W1[(NRBF_+FF)*HH + e];
        S.Wsum[1][e] = s2W1[NRBF_*HH + e] + s2W1[(NRBF_+FF)*HH + e];
        S.Wsum[2][e] = fW1[NRBF_*HH + e];
    }
    for (int e = tid; e < HH*FF; e += NT) S.fW2s[e] = fW2[e];
    if (tid < HH) {
        S.bsum[0][tid] = s1b1[tid];
        S.bsum[1][tid] = s2b1[tid];
        S.bsum[2][tid] = fb1[tid];
    }
    if (tid < FF)    S.fb2s[tid] = fb2[tid];
    if (tid < NRBF_) S.ms[tid]   = mus[tid];

    // Per-thread second-layer weights & bias for this thread's 4 h-indices
    float wv[4];
    #pragma unroll
    for (int q = 0; q < 4; q++)
        wv[q] = hf ? s2W2[tx*4 + q] : s1W2[tx*4 + q];
    const float b2 = hf ? s2b2[0] : s1b2[0];

    for (int bi = blockIdx.x; bi < BN*NPT; bi += gridDim.x) {
        const int b = bi >> 8;
        const int i = bi & 255;
        const float* st = state + b*STRIDE_B;
        __syncthreads();   // also covers weight staging on first iter
        for (int e = tid; e < NPT*3; e += NT) S.xs[e] = st[e];
        if (tid < FF) S.feats_s[tid] = st[NPT*3 + i*FF + tid];
        __syncthreads();

        if (ty == 0) {  // softmax(feats_i) over F=32 by warp 0
            float v = S.feats_s[tx];
            float m = v;
            #pragma unroll
            for (int o = 16; o; o >>= 1) m = fmaxf(m, __shfl_xor_sync(0xffffffffu, m, o));
            float e = __expf(v - m);
            float s = e;
            #pragma unroll
            for (int o = 16; o; o >>= 1) s += __shfl_xor_sync(0xffffffffu, s, o);
            S.smax[tx] = e / s;
        }
        __syncthreads();

        // Per-(b,i) constant part of hidden pre-activations (3 nets x 128 h)
        if (tid < 3*HH) {
            int net = tid >> 7, h = tid & 127;
            const float* fv = (net < 2) ? S.feats_s : S.smax;
            const float* Wn = S.Wsum[net];
            float c = S.bsum[net][h];
            #pragma unroll
            for (int f = 0; f < FF; f++) c += fv[f] * Wn[f*HH + h];
            S.cvec[net][h] = c;
        }
        __syncthreads();

        // cA: half0 -> c1, half1 -> c2.  cB: half1 -> cf.
        float cA[4], cB[4];
        #pragma unroll
        for (int q = 0; q < 4; q++) {
            cA[q] = hf ? S.cvec[1][tx*4 + q] : S.cvec[0][tx*4 + q];
            cB[q] = hf ? S.cvec[2][tx*4 + q] : 0.f;
        }
        const float xi0 = S.xs[i*3+0], xi1 = S.xs[i*3+1], xi2 = S.xs[i*3+2];

        float accf0=0.f, accf1=0.f, accf2=0.f, accf3=0.f;   // half1: f-silu sums per h
        float vx0=0.f, vy0=0.f, vz0=0.f;                     // half0
        float wxa=0.f, wya=0.f, wza=0.f;                     // half1
        float trc=0.f;                                       // half0

        for (int tile = 0; tile < 4; tile++) {
            if (tid < 64) {
                int gp = tile*64 + tid;
                float r0 = 0.f, r1 = 0.f, r2 = 0.f;
                if (gp < NM1) {
                    int j = (gp < i) ? gp : gp + 1;
                    r0 = xi0 - S.xs[j*3+0];
                    r1 = xi1 - S.xs[j*3+1];
                    r2 = xi2 - S.xs[j*3+2];
                }
                S.pd[tid] = sqrtf(r0*r0 + r1*r1 + r2*r2 + EPSV);
                S.pr[tid*3+0] = r0; S.pr[tid*3+1] = r1; S.pr[tid*3+2] = r2;
            }
            __syncthreads();
            for (int e = tid; e < NK2*64; e += NT) {
                int k2 = e >> 6, p = e & 63;
                float d = S.pd[p];
                float t0 = d - S.ms[2*k2];
                float t1 = d - S.ms[2*k2+1];
                float a0 = __expf(-gamma * t0 * t0);
                float a1 = __expf(-gamma * t1 * t1);
                ulonglong2 v; v.x = pack2(a0); v.y = pack2(a1);
                S.A2q[e] = v;
            }
            __syncthreads();

            // GEMM: warp (g,hf): pairs g*8..g*8+7  x  cols [hf*256, hf*256+256)
            // acc0: block A cols (s1 or s2), acc1: block B cols (psi or f)
            ull acc0[8][2], acc1[8][2];
            #pragma unroll
            for (int p = 0; p < 8; p++) {
                acc0[p][0]=0ull; acc0[p][1]=0ull;
                acc1[p][0]=0ull; acc1[p][1]=0ull;
            }

            const ulonglong2* Apk = S.A2q + g*8;             // [k2][64]
            const ull* Wu = reinterpret_cast<const ull*>(S.Wc) + hf*128 + tx*2;
            #pragma unroll 5
            for (int k2 = 0; k2 < NK2; k2++) {
                ulonglong2 b0a = *reinterpret_cast<const ulonglong2*>(Wu + (2*k2)*256);
                ulonglong2 b0b = *reinterpret_cast<const ulonglong2*>(Wu + (2*k2)*256 + 64);
                ulonglong2 b1a = *reinterpret_cast<const ulonglong2*>(Wu + (2*k2+1)*256);
                ulonglong2 b1b = *reinterpret_cast<const ulonglong2*>(Wu + (2*k2+1)*256 + 64);
                #pragma unroll
                for (int pg = 0; pg < 2; pg++) {             // 4 pairs at a time (reg pressure)
                    ulonglong2 av[4];
                    #pragma unroll
                    for (int p = 0; p < 4; p++) av[p] = Apk[k2*64 + pg*4 + p];  // broadcast
                    #pragma unroll
                    for (int p = 0; p < 4; p++) {
                        int pp = pg*4 + p;
                        ffma2(acc0[pp][0], b0a.x, av[p].x);
                        ffma2(acc0[pp][1], b0a.y, av[p].x);
                        ffma2(acc1[pp][0], b0b.x, av[p].x);
                        ffma2(acc1[pp][1], b0b.y, av[p].x);
                        ffma2(acc0[pp][0], b1a.x, av[p].y);
                        ffma2(acc0[pp][1], b1a.y, av[p].y);
                        ffma2(acc1[pp][0], b1b.x, av[p].y);
                        ffma2(acc1[pp][1], b1b.y, av[p].y);
                    }
                }
            }

            // Epilogue
            #pragma unroll
            for (int p = 0; p < 8; p++) {
                int lp = g*8 + p;
                int gp = tile*64 + lp;
                float d  = S.pd[lp];
                float r0 = S.pr[lp*3+0], r1 = S.pr[lp*3+1], r2 = S.pr[lp*3+2];
                if (hf == 0) {
                    // s1 + exact d-gradient (phi1 = acc0, psi = acc1)
                    float sA = 0.f, gA = 0.f;
                    #pragma unroll
                    for (int u = 0; u < 2; u++) {
                        float2 vA = unpack2(acc0[p][u]);
                        float2 vB = unpack2(acc1[p][u]);
                        #pragma unroll
                        for (int sub = 0; sub < 2; sub++) {
                            int q = u*2 + sub;
                            float phi1 = sub ? vA.y : vA.x;
                            float psi  = sub ? vB.y : vB.x;
                            float pre1 = phi1 + cA[q];
                            float sig  = __fdividef(1.f, 1.f + __expf(-pre1));
                            sA += pre1 * sig * wv[q];
                            float dsil = sig * (1.f + pre1 * (1.f - sig));
                            gA += wv[q] * dsil * (d * phi1 - psi);
                        }
                    }
                    #pragma unroll
                    for (int o = 16; o; o >>= 1) {
                        sA += __shfl_xor_sync(0xffffffffu, sA, o);
                        gA += __shfl_xor_sync(0xffffffffu, gA, o);
                    }
                    if (gp < NM1) {
                        float s1 = sA + b2;
                        float r2d = __fdividef(d*d - EPSV, d);   // |r|^2 / d
                        vx0 += r0*s1; vy0 += r1*s1; vz0 += r2*s1;
                        trc += r2d * (n2g * gA) + 3.f * s1;
                    }
                } else {
                    // s2 (acc0) + f-net silu accumulation (acc1)
                    float sB = 0.f;
                    float afq[4];
                    #pragma unroll
                    for (int u = 0; u < 2; u++) {
                        float2 vA = unpack2(acc0[p][u]);
                        float2 vB = unpack2(acc1[p][u]);
                        #pragma unroll
                        for (int sub = 0; sub < 2; sub++) {
                            int q = u*2 + sub;
                            float phi2 = sub ? vA.y : vA.x;
                            float phif = sub ? vB.y : vB.x;
                            float pre2 = phi2 + cA[q];
                            float sig2 = __fdividef(1.f, 1.f + __expf(-pre2));
                            sB += pre2 * sig2 * wv[q];
                            float pref = phif + cB[q];
                            float sigf = __fdividef(1.f, 1.f + __expf(-pref));
                            afq[q] = pref * sigf;
                        }
                    }
                    #pragma unroll
                    for (int o = 16; o; o >>= 1)
                        sB += __shfl_xor_sync(0xffffffffu, sB, o);
                    if (gp < NM1) {
                        float s2 = sB + b2;
                        wxa += r0*s2; wya += r1*s2; wza += r2*s2;
                        accf0 += afq[0]; accf1 += afq[1]; accf2 += afq[2]; accf3 += afq[3];
                    }
                }
            }
            __syncthreads();
        } // tiles

        // Combine per-warp partials
        if (hf == 1) {
            S.accst[g][tx*4+0] = accf0;
            S.accst[g][tx*4+1] = accf1;
            S.accst[g][tx*4+2] = accf2;
            S.accst[g][tx*4+3] = accf3;
        }
        if (tx == 0) {
            S.wpart[ty][0] = vx0; S.wpart[ty][1] = vy0; S.wpart[ty][2] = vz0;
            S.wpart[ty][3] = wxa; S.wpart[ty][4] = wya; S.wpart[ty][5] = wza;
            S.wpart[ty][6] = trc;
        }
        __syncthreads();
        if (tid < HH) {
            float t = 0.f;
            #pragma unroll
            for (int w = 0; w < 8; w++) t += S.accst[w][tid];
            S.accst[0][tid] = t;
        }
        __syncthreads();
        if (tid < FF) {
            float s = 0.f;
            for (int h = 0; h < HH; h++) s += S.accst[0][h] * S.fW2s[h*FF + tid];
            out[b*STRIDE_B + NPT*3 + i*FF + tid] = S.fb2s[tid] + s * (1.f/255.f);
        }
        if (tid == 0) {
            float v0=0,v1=0,v2=0,w0=0,w1=0,w2=0,tr=0;
            #pragma unroll
            for (int w = 0; w < NW; w++) {
                v0 += S.wpart[w][0]; v1 += S.wpart[w][1]; v2 += S.wpart[w][2];
                w0 += S.wpart[w][3]; w1 += S.wpart[w][4]; w2 += S.wpart[w][5];
                tr += S.wpart[w][6];
            }
            const float inv = 1.f/255.f;
            v0 *= inv; v1 *= inv; v2 *= inv;
            w0 *= inv; w1 *= inv; w2 *= inv;
            // v_x = vx0 + cross(w, vx0)   (linearity of the Levi-Civita term)
            float fx = v0 + (w1*v2 - w2*v1);
            float fy = v1 + (w2*v0 - w0*v2);
            float fz = v2 + (w0*v1 - w1*v0);
            g_vxf[bi*3+0] = fx; g_vxf[bi*3+1] = fy; g_vxf[bi*3+2] = fz;
            g_tr[bi] = tr * inv;
        }
    }

    // ---- Last-block finalization: mean removal + trace ----
    __syncthreads();
    if (tid == 0) {
        __threadfence();
        int v = atomicAdd(&g_done, 1);
        S.lastflag = (v == (int)gridDim.x - 1) ? 1.f : 0.f;
    }
    __syncthreads();
    if (S.lastflag != 0.f) {
        __threadfence();
        if (ty < BN) {   // warp ty sums batch b = ty
            float s0 = 0.f, s1 = 0.f, s2 = 0.f, st = 0.f;
            for (int ii = tx; ii < NPT; ii += 32) {
                int e = ty*NPT + ii;
                s0 += g_vxf[e*3+0]; s1 += g_vxf[e*3+1]; s2 += g_vxf[e*3+2];
                st += g_tr[e];
            }
            #pragma unroll
            for (int o = 16; o; o >>= 1) {
                s0 += __shfl_xor_sync(0xffffffffu, s0, o);
                s1 += __shfl_xor_sync(0xffffffffu, s1, o);
                s2 += __shfl_xor_sync(0xffffffffu, s2, o);
                st += __shfl_xor_sync(0xffffffffu, st, o);
            }
            if (tx == 0) {
                S.fin[ty*4+0] = s0 * (1.f/NPT);
                S.fin[ty*4+1] = s1 * (1.f/NPT);
                S.fin[ty*4+2] = s2 * (1.f/NPT);
                S.fin[ty*4+3] = st;
            }
        }
        __syncthreads();
        for (int e = tid; e < BN*NPT; e += NT) {
            int bb = e >> 8, ii = e & 255;
            float m0 = S.fin[bb*4+0], m1 = S.fin[bb*4+1], m2 = S.fin[bb*4+2];
            out[bb*STRIDE_B + ii*3+0] = g_vxf[e*3+0] - m0;
            out[bb*STRIDE_B + ii*3+1] = g_vxf[e*3+1] - m1;
            out[bb*STRIDE_B + ii*3+2] = g_vxf[e*3+2] - m2;
        }
        if (tid < BN) out[BN*STRIDE_B + tid] = S.fin[tid*4+3];
        if (tid == 0) g_done = 0;   // self-reset for next launch
    }
}

extern "C" void kernel_launch(void* const* d_in, const int* in_sizes, int n_in,
                              void* d_out, int out_size) {
    (void)in_sizes; (void)n_in; (void)out_size;
    const float* state = (const float*)d_in[1];
    const float* mus   = (const float*)d_in[2];
    const float* gamma = (const float*)d_in[3];
    const float* s1W1  = (const float*)d_in[4];
    const float* s1b1  = (const float*)d_in[5];
    const float* s1W2  = (const float*)d_in[6];
    const float* s1b2  = (const float*)d_in[7];
    const float* s2W1  = (const float*)d_in[8];
    const float* s2b1  = (const float*)d_in[9];
    const float* s2W2  = (const float*)d_in[10];
    const float* s2b2  = (const float*)d_in[11];
    const float* fW1   = (const float*)d_in[12];
    const float* fb1   = (const float*)d_in[13];
    const float* fW2   = (const float*)d_in[14];
    const float* fb2   = (const float*)d_in[15];
    float* out = (float*)d_out;

    const size_t smem = sizeof(SmemLayout);
    cudaFuncSetAttribute(k_main, cudaFuncAttributeMaxDynamicSharedMemorySize, (int)smem);

    k_main<<<NCTA, NT, smem>>>(state, mus, gamma,
                               s1W1, s1b1, s1W2, s1b2,
                               s2W1, s2b1, s2W2, s2b2,
                               fW1, fb1, fW2, fb2, out);
}

// round 10
// speedup vs baseline: 1.0849x; 1.0521x over previous
#include <cuda_runtime.h>

typedef unsigned long long ull;

#define BN 8
#define NPT 256
#define FF 32
#define NRBF_ 50
#define NK2 25
#define HH 128
#define NM1 255
#define NCOL 512
#define EPSV 1e-6f
#define STRIDE_B (NPT*3 + NPT*FF)   /* 8960 */
#define NCTA 152
#define NT 512
#define NW 16

__device__ float g_vxf[BN*NPT*3];
__device__ float g_tr[BN*NPT];
__device__ int   g_done = 0;

// Wc column layout: [0:128)=s1W  [128:256)=mu*s1W  [256:384)=s2W  [384:512)=fW
struct SmemLayout {
    float      Wc[NRBF_*NCOL];    // 102400 B
    ulonglong2 A2g[8*NK2*8];      // [group][k2][pair] dup-packed rbf   25600 B
    float      Wsum[3][FF*HH];    // 49152 B
    float      fW2s[HH*FF];       // 16384 B
    float      bsum[3][HH];
    float      fb2s[FF];
    float      xs[NPT*3];
    float      ms[NRBF_ + 2];
    float      pd[64];
    float      pdi[64];
    float      pr[64*3];
    float      feats_s[FF];
    float      smax[FF];
    float      cvec[3][HH];
    float      accst[8][HH];
    float      wpart[NW][8];
    float      fin[BN*4];
    float      lastflag;
};

__device__ __forceinline__ float2 unpack2(ull v) {
    float2 r; asm("mov.b64 {%0, %1}, %2;" : "=f"(r.x), "=f"(r.y) : "l"(v)); return r;
}
__device__ __forceinline__ ull pack2(float x) {
    ull r; asm("mov.b64 %0, {%1, %1};" : "=l"(r) : "f"(x)); return r;
}
__device__ __forceinline__ void ffma2(ull &d, ull a, ull b) {
    asm("fma.rn.f32x2 %0, %1, %2, %3;" : "=l"(d) : "l"(a), "l"(b), "l"(d));
}
#define NB(id) asm volatile("bar.sync %0, %1;" :: "r"(id), "r"(64) : "memory")

__global__ __launch_bounds__(NT, 1) void k_main(
    const float* __restrict__ state,
    const float* __restrict__ mus,
    const float* __restrict__ gammap,
    const float* __restrict__ s1W1, const float* __restrict__ s1b1,
    const float* __restrict__ s1W2, const float* __restrict__ s1b2,
    const float* __restrict__ s2W1, const float* __restrict__ s2b1,
    const float* __restrict__ s2W2, const float* __restrict__ s2b2,
    const float* __restrict__ fW1,  const float* __restrict__ fb1,
    const float* __restrict__ fW2,  const float* __restrict__ fb2,
    float* __restrict__ out)
{
    extern __shared__ char smraw[];
    SmemLayout& S = *reinterpret_cast<SmemLayout*>(smraw);
    const int tid = threadIdx.x;
    const int tx  = tid & 31;
    const int ty  = tid >> 5;
    const int g   = ty >> 1;     // pair-group 0..7 (owns pairs g*8..g*8+7 of each tile)
    const int hf  = ty & 1;      // column half: 0 -> s1|psi, 1 -> s2|f
    const float gamma = gammap[0];
    const float n2g   = -2.0f * gamma;

    // ---- One-time per-CTA weight staging ----
    for (int e = tid; e < NRBF_*HH; e += NT) {
        int k = e >> 7, h = e & 127;
        float w1 = s1W1[e];
        S.Wc[k*NCOL + h]       = w1;
        S.Wc[k*NCOL + 128 + h] = mus[k] * w1;
        S.Wc[k*NCOL + 256 + h] = s2W1[e];
        S.Wc[k*NCOL + 384 + h] = fW1[e];
    }
    for (int e = tid; e < FF*HH; e += NT) {
        S.Wsum[0][e] = s1W1[NRBF_*HH + e] + s1W1[(NRBF_+FF)*HH + e];
        S.Wsum[1][e] = s2W1[NRBF_*HH + e] + s2W1[(NRBF_+FF)*HH + e];
        S.Wsum[2][e] = fW1[NRBF_*HH + e];
    }
    for (int e = tid; e < HH*FF; e += NT) S.fW2s[e] = fW2[e];
    if (tid < HH) {
        S.bsum[0][tid] = s1b1[tid];
        S.bsum[1][tid] = s2b1[tid];
        S.bsum[2][tid] = fb1[tid];
    }
    if (tid < FF)    S.fb2s[tid] = fb2[tid];
    if (tid < NRBF_) S.ms[tid]   = mus[tid];

    float wv[4];
    #pragma unroll
    for (int q = 0; q < 4; q++)
        wv[q] = hf ? s2W2[tx*4 + q] : s1W2[tx*4 + q];
    const float b2 = hf ? s2b2[0] : s1b2[0];
    const float nv = 32.f - ((g == 7) ? 1.f : 0.f);   // valid pairs per group per bi

    for (int bi = blockIdx.x; bi < BN*NPT; bi += gridDim.x) {
        const int b = bi >> 8;
        const int i = bi & 255;
        const float* st = state + b*STRIDE_B;
        __syncthreads();   // xs/A2g/pd reuse across bi; weight staging on first iter
        for (int e = tid; e < NPT*3; e += NT) S.xs[e] = st[e];
        if (tid < FF) S.feats_s[tid] = st[NPT*3 + i*FF + tid];
        __syncthreads();

        if (ty == 0) {  // softmax(feats_i) over F=32 by warp 0
            float v = S.feats_s[tx];
            float m = v;
            #pragma unroll
            for (int o = 16; o; o >>= 1) m = fmaxf(m, __shfl_xor_sync(0xffffffffu, m, o));
            float e = __expf(v - m);
            float s = e;
            #pragma unroll
            for (int o = 16; o; o >>= 1) s += __shfl_xor_sync(0xffffffffu, s, o);
            S.smax[tx] = e / s;
        }
        __syncthreads();

        // Per-(b,i) constant part of hidden pre-activations (3 nets x 128 h)
        if (tid < 3*HH) {
            int net = tid >> 7, h = tid & 127;
            const float* fv = (net < 2) ? S.feats_s : S.smax;
            const float* Wn = S.Wsum[net];
            float c = S.bsum[net][h];
            #pragma unroll
            for (int f = 0; f < FF; f++) c += fv[f] * Wn[f*HH + h];
            S.cvec[net][h] = c;
        }
        __syncthreads();

        float cA[4], cB[4];
        #pragma unroll
        for (int q = 0; q < 4; q++) {
            cA[q] = hf ? S.cvec[1][tx*4 + q] : S.cvec[0][tx*4 + q];
            cB[q] = hf ? S.cvec[2][tx*4 + q] : 0.f;
        }
        const float xi0 = S.xs[i*3+0], xi1 = S.xs[i*3+1], xi2 = S.xs[i*3+2];

        // In-lane accumulators (no per-pair reductions)
        float a0=0.f, a1=0.f, a2=0.f, at=0.f;     // hf0: r*s1-partial + trace; hf1: r*s2-partial
        float rs0=0.f, rs1=0.f, rs2=0.f;           // uniform sum of r over valid pairs
        float accf0=0.f, accf1=0.f, accf2=0.f, accf3=0.f;  // hf1: f-silu per-h sums

        for (int tile = 0; tile < 4; tile++) {
            NB(g+1);   // both warps of group g done with prior tile's pd/A2g reads
            if (hf == 0 && tx < 8) {
                int lp = g*8 + tx;
                int gp = tile*64 + lp;
                float r0 = 0.f, r1 = 0.f, r2 = 0.f;
                if (gp < NM1) {
                    int j = (gp < i) ? gp : gp + 1;
                    r0 = xi0 - S.xs[j*3+0];
                    r1 = xi1 - S.xs[j*3+1];
                    r2 = xi2 - S.xs[j*3+2];
                }
                float d2 = r0*r0 + r1*r1 + r2*r2 + EPSV;
                float ri = rsqrtf(d2);
                S.pd[lp]  = d2 * ri;
                S.pdi[lp] = ri;
                S.pr[lp*3+0] = r0; S.pr[lp*3+1] = r1; S.pr[lp*3+2] = r2;
            }
            NB(g+1);   // pd ready for both warps
            {   // rbf production: hf0 -> k2 0..12, hf1 -> k2 13..24, for this group's 8 pairs
                const int k2base = hf ? 13 : 0;
                const int nelem  = (hf ? 12 : 13) * 8;
                for (int e = tx; e < nelem; e += 32) {
                    int k2 = k2base + (e >> 3);
                    int p  = e & 7;
                    float d  = S.pd[g*8 + p];
                    float t0 = d - S.ms[2*k2];
                    float t1 = d - S.ms[2*k2+1];
                    ulonglong2 v;
                    v.x = pack2(__expf(-gamma * t0 * t0));
                    v.y = pack2(__expf(-gamma * t1 * t1));
                    S.A2g[(g*NK2 + k2)*8 + p] = v;
                }
            }
            NB(g+1);   // A slice ready

            // GEMM: pairs g*8..g*8+7  x  cols [hf*256, hf*256+256)
            ull acc0[8][2], acc1[8][2];
            #pragma unroll
            for (int p = 0; p < 8; p++) {
                acc0[p][0]=0ull; acc0[p][1]=0ull;
                acc1[p][0]=0ull; acc1[p][1]=0ull;
            }
            const ulonglong2* Ag = S.A2g + g*(NK2*8);
            const ull* Wu = reinterpret_cast<const ull*>(S.Wc) + hf*128 + tx*2;
            #pragma unroll 5
            for (int k2 = 0; k2 < NK2; k2++) {
                ulonglong2 b0a = *reinterpret_cast<const ulonglong2*>(Wu + (2*k2)*256);
                ulonglong2 b0b = *reinterpret_cast<const ulonglong2*>(Wu + (2*k2)*256 + 64);
                ulonglong2 b1a = *reinterpret_cast<const ulonglong2*>(Wu + (2*k2+1)*256);
                ulonglong2 b1b = *reinterpret_cast<const ulonglong2*>(Wu + (2*k2+1)*256 + 64);
                #pragma unroll
                for (int pg = 0; pg < 2; pg++) {
                    ulonglong2 av[4];
                    #pragma unroll
                    for (int p = 0; p < 4; p++) av[p] = Ag[k2*8 + pg*4 + p];  // broadcast
                    #pragma unroll
                    for (int p = 0; p < 4; p++) {
                        int pp = pg*4 + p;
                        ffma2(acc0[pp][0], b0a.x, av[p].x);
                        ffma2(acc0[pp][1], b0a.y, av[p].x);
                        ffma2(acc1[pp][0], b0b.x, av[p].x);
                        ffma2(acc1[pp][1], b0b.y, av[p].x);
                        ffma2(acc0[pp][0], b1a.x, av[p].y);
                        ffma2(acc0[pp][1], b1a.y, av[p].y);
                        ffma2(acc1[pp][0], b1b.x, av[p].y);
                        ffma2(acc1[pp][1], b1b.y, av[p].y);
                    }
                }
            }

            // Epilogue: in-lane accumulation, zero shuffles
            #pragma unroll
            for (int p = 0; p < 8; p++) {
                int lp = g*8 + p;
                int gp = tile*64 + lp;
                float d  = S.pd[lp];
                float ri = S.pdi[lp];
                float r0 = S.pr[lp*3+0], r1 = S.pr[lp*3+1], r2 = S.pr[lp*3+2];
                bool valid = (gp < NM1);
                if (hf == 0) {
                    float sc = 0.f, gc = 0.f;
                    #pragma unroll
                    for (int u = 0; u < 2; u++) {
                        float2 vA = unpack2(acc0[p][u]);
                        float2 vB = unpack2(acc1[p][u]);
                        #pragma unroll
                        for (int sub = 0; sub < 2; sub++) {
                            int q = u*2 + sub;
                            float phi1 = sub ? vA.y : vA.x;
                            float psi  = sub ? vB.y : vB.x;
                            float pre1 = phi1 + cA[q];
                            float sig  = __fdividef(1.f, 1.f + __expf(-pre1));
                            sc += pre1 * sig * wv[q];
                            float dsil = sig * (1.f + pre1 * (1.f - sig));
                            gc += wv[q] * dsil * (d * phi1 - psi);
                        }
                    }
                    if (valid) {
                        a0 += r0*sc; a1 += r1*sc; a2 += r2*sc;
                        float r2d = (d*d - EPSV) * ri;          // |r|^2 / d
                        at += r2d * (n2g * gc) + 3.f * sc;
                        rs0 += r0; rs1 += r1; rs2 += r2;
                    }
                } else {
                    float sc = 0.f;
                    float afq[4];
                    #pragma unroll
                    for (int u = 0; u < 2; u++) {
                        float2 vA = unpack2(acc0[p][u]);
                        float2 vB = unpack2(acc1[p][u]);
                        #pragma unroll
                        for (int sub = 0; sub < 2; sub++) {
                            int q = u*2 + sub;
                            float phi2 = sub ? vA.y : vA.x;
                            float phif = sub ? vB.y : vB.x;
                            float pre2 = phi2 + cA[q];
                            float sig2 = __fdividef(1.f, 1.f + __expf(-pre2));
                            sc += pre2 * sig2 * wv[q];
                            float pref = phif + cB[q];
                            float sigf = __fdividef(1.f, 1.f + __expf(-pref));
                            afq[q] = pref * sigf;
                        }
                    }
                    if (valid) {
                        a0 += r0*sc; a1 += r1*sc; a2 += r2*sc;
                        accf0 += afq[0]; accf1 += afq[1]; accf2 += afq[2]; accf3 += afq[3];
                        rs0 += r0; rs1 += r1; rs2 += r2;
                    }
                }
            }
        } // tiles

        // Per-warp: single reduction per bi
        #pragma unroll
        for (int o = 16; o; o >>= 1) {
            a0 += __shfl_xor_sync(0xffffffffu, a0, o);
            a1 += __shfl_xor_sync(0xffffffffu, a1, o);
            a2 += __shfl_xor_sync(0xffffffffu, a2, o);
            at += __shfl_xor_sync(0xffffffffu, at, o);
        }
        float c0 = a0 + b2*rs0;     // hf0: vx partial; hf1: wx partial (identical formula)
        float c1 = a1 + b2*rs1;
        float c2 = a2 + b2*rs2;
        float ct = at + 3.f*b2*nv;  // trace partial (hf0 only)

        if (hf == 1) {
            S.accst[g][tx*4+0] = accf0;
            S.accst[g][tx*4+1] = accf1;
            S.accst[g][tx*4+2] = accf2;
            S.accst[g][tx*4+3] = accf3;
        }
        if (tx == 0) {
            if (hf == 0) {
                S.wpart[ty][0] = c0; S.wpart[ty][1] = c1; S.wpart[ty][2] = c2;
                S.wpart[ty][3] = 0.f; S.wpart[ty][4] = 0.f; S.wpart[ty][5] = 0.f;
                S.wpart[ty][6] = ct;
            } else {
                S.wpart[ty][0] = 0.f; S.wpart[ty][1] = 0.f; S.wpart[ty][2] = 0.f;
                S.wpart[ty][3] = c0; S.wpart[ty][4] = c1; S.wpart[ty][5] = c2;
                S.wpart[ty][6] = 0.f;
            }
        }
        __syncthreads();
        if (tid < HH) {
            float t = 0.f;
            #pragma unroll
            for (int w = 0; w < 8; w++) t += S.accst[w][tid];
            S.accst[0][tid] = t;
        }
        __syncthreads();
        if (tid < FF) {
            float s = 0.f;
            for (int h = 0; h < HH; h++) s += S.accst[0][h] * S.fW2s[h*FF + tid];
            out[b*STRIDE_B + NPT*3 + i*FF + tid] = S.fb2s[tid] + s * (1.f/255.f);
        }
        if (tid == 0) {
            float v0=0,v1=0,v2=0,w0=0,w1=0,w2=0,tr=0;
            #pragma unroll
            for (int w = 0; w < NW; w++) {
                v0 += S.wpart[w][0]; v1 += S.wpart[w][1]; v2 += S.wpart[w][2];
                w0 += S.wpart[w][3]; w1 += S.wpart[w][4]; w2 += S.wpart[w][5];
                tr += S.wpart[w][6];
            }
            const float inv = 1.f/255.f;
            v0 *= inv; v1 *= inv; v2 *= inv;
            w0 *= inv; w1 *= inv; w2 *= inv;
            // v_x = vx0 + cross(w, vx0)   (linearity of the Levi-Civita term)
            float fx = v0 + (w1*v2 - w2*v1);
            float fy = v1 + (w2*v0 - w0*v2);
            float fz = v2 + (w0*v1 - w1*v0);
            g_vxf[bi*3+0] = fx; g_vxf[bi*3+1] = fy; g_vxf[bi*3+2] = fz;
            g_tr[bi] = tr * inv;
        }
    }

    // ---- Last-block finalization: mean removal + trace ----
    __syncthreads();
    if (tid == 0) {
        __threadfence();
        int v = atomicAdd(&g_done, 1);
        S.lastflag = (v == (int)gridDim.x - 1) ? 1.f : 0.f;
    }
    __syncthreads();
    if (S.lastflag != 0.f) {
        __threadfence();
        if (ty < BN) {   // warp ty sums batch b = ty
            float s0 = 0.f, s1 = 0.f, s2 = 0.f, st = 0.f;
            for (int ii = tx; ii < NPT; ii += 32) {
                int e = ty*NPT + ii;
                s0 += g_vxf[e*3+0]; s1 += g_vxf[e*3+1]; s2 += g_vxf[e*3+2];
                st += g_tr[e];
            }
            #pragma unroll
            for (int o = 16; o; o >>= 1) {
                s0 += __shfl_xor_sync(0xffffffffu, s0, o);
                s1 += __shfl_xor_sync(0xffffffffu, s1, o);
                s2 += __shfl_xor_sync(0xffffffffu, s2, o);
                st += __shfl_xor_sync(0xffffffffu, st, o);
            }
            if (tx == 0) {
                S.fin[ty*4+0] = s0 * (1.f/NPT);
                S.fin[ty*4+1] = s1 * (1.f/NPT);
                S.fin[ty*4+2] = s2 * (1.f/NPT);
                S.fin[ty*4+3] = st;
            }
        }
        __syncthreads();
        for (int e = tid; e < BN*NPT; e += NT) {
            int bb = e >> 8, ii = e & 255;
            float m0 = S.fin[bb*4+0], m1 = S.fin[bb*4+1], m2 = S.fin[bb*4+2];
            out[bb*STRIDE_B + ii*3+0] = g_vxf[e*3+0] - m0;
            out[bb*STRIDE_B + ii*3+1] = g_vxf[e*3+1] - m1;
            out[bb*STRIDE_B + ii*3+2] = g_vxf[e*3+2] - m2;
        }
        if (tid < BN) out[BN*STRIDE_B + tid] = S.fin[tid*4+3];
        if (tid == 0) g_done = 0;   // self-reset for next launch
    }
}

extern "C" void kernel_launch(void* const* d_in, const int* in_sizes, int n_in,
                              void* d_out, int out_size) {
    (void)in_sizes; (void)n_in; (void)out_size;
    const float* state = (const float*)d_in[1];
    const float* mus   = (const float*)d_in[2];
    const float* gamma = (const float*)d_in[3];
    const float* s1W1  = (const float*)d_in[4];
    const float* s1b1  = (const float*)d_in[5];
    const float* s1W2  = (const float*)d_in[6];
    const float* s1b2  = (const float*)d_in[7];
    const float* s2W1  = (const float*)d_in[8];
    const float* s2b1  = (const float*)d_in[9];
    const float* s2W2  = (const float*)d_in[10];
    const float* s2b2  = (const float*)d_in[11];
    const float* fW1   = (const float*)d_in[12];
    const float* fb1   = (const float*)d_in[13];
    const float* fW2   = (const float*)d_in[14];
    const float* fb2   = (const float*)d_in[15];
    float* out = (float*)d_out;

    const size_t smem = sizeof(SmemLayout);
    cudaFuncSetAttribute(k_main, cudaFuncAttributeMaxDynamicSharedMemorySize, (int)smem);

    k_main<<<NCTA, NT, smem>>>(state, mus, gamma,
                               s1W1, s1b1, s1W2, s1b2,
                               s2W1, s2b1, s2W2, s2b2,
                               fW1, fb1, fW2, fb2, out);
}

// round 17
// speedup vs baseline: 1.8530x; 1.7080x over previous
#include <cuda_runtime.h>

typedef unsigned long long ull;

#define BN 8
#define NPT 256
#define FF 32
#define NRBF_ 50
#define HH 128
#define NM1 255
#define EPSV 1e-6f
#define STRIDE_B (NPT*3 + NPT*FF)   /* 8960 */
#define NCTA 152
#define NT 512
#define NW 16

#define NROW 99          /* storage rows: row r <-> d=(r-1)*H, r=0..98 */
#define IDXMAX 95        /* clamp: taps at storage rows idx..idx+3 <= 98 */
#define HSTEP 0.068f
#define INVH (1.0f/0.068f)

__device__ float g_vxf[BN*NPT*3];
__device__ float g_tr[BN*NPT];
__device__ int   g_done = 0;

// Table row layout (512 floats): [0:128)=V1(s1) [128:256)=G(ds1/dd) [256:384)=V2(s2) [384:512)=Vf(f)
struct SmemLayout {
    float T[NROW*512];        // 202752 B
    float ws[16][104];        // per-warp e/em scratch for table build (6656 B)
    float xs[NPT*3];
    float cvec[3][HH];
    float pd[64];
    float pdi[64];
    float pr[64*3];
    int   pidx[64];
    ull   pw[64][4];          // dup-packed Lagrange weights
    float feats_s[FF];
    float smax[FF];
    float accst[8][HH];
    float wpart[NW][8];
    float fin[BN*4];
    float lastflag;
};

__device__ __forceinline__ float2 unpack2(ull v) {
    float2 r; asm("mov.b64 {%0, %1}, %2;" : "=f"(r.x), "=f"(r.y) : "l"(v)); return r;
}
__device__ __forceinline__ ull pack2(float x) {
    ull r; asm("mov.b64 %0, {%1, %1};" : "=l"(r) : "f"(x)); return r;
}
__device__ __forceinline__ void ffma2(ull &d, ull a, ull b) {
    asm("fma.rn.f32x2 %0, %1, %2, %3;" : "=l"(d) : "l"(a), "l"(b), "l"(d));
}
#define NB(id) asm volatile("bar.sync %0, %1;" :: "r"(id), "r"(64) : "memory")

__global__ __launch_bounds__(NT, 1) void k_main(
    const float* __restrict__ state,
    const float* __restrict__ mus,
    const float* __restrict__ gammap,
    const float* __restrict__ s1W1, const float* __restrict__ s1b1,
    const float* __restrict__ s1W2, const float* __restrict__ s1b2,
    const float* __restrict__ s2W1, const float* __restrict__ s2b1,
    const float* __restrict__ s2W2, const float* __restrict__ s2b2,
    const float* __restrict__ fW1,  const float* __restrict__ fb1,
    const float* __restrict__ fW2,  const float* __restrict__ fb2,
    float* __restrict__ out)
{
    extern __shared__ char smraw[];
    SmemLayout& S = *reinterpret_cast<SmemLayout*>(smraw);
    const int tid = threadIdx.x;
    const int tx  = tid & 31;
    const int ty  = tid >> 5;
    const int g   = ty >> 1;     // pair-group 0..7
    const int hf  = ty & 1;      // column half: 0 -> V1|G, 1 -> V2|Vf
    const float gamma = gammap[0];

    // ---- One-time table build: T[r][c], warp ty owns rows ty, ty+16, ... ----
    {
        float* wse = S.ws[ty];
        for (int r = ty; r < NROW; r += NW) {
            float dr = (float)(r - 1) * HSTEP;
            __syncwarp();
            for (int k = tx; k < NRBF_; k += 32) {
                float mu = mus[k];
                float t  = dr - mu;
                float e  = expf(-gamma * t * t);
                wse[k]      = e;
                wse[52 + k] = -2.f * gamma * t * e;
            }
            __syncwarp();
            for (int cc = tx; cc < 512; cc += 32) {
                int blk = cc >> 7, h = cc & 127;
                const float* W  = (blk <= 1) ? s1W1 : ((blk == 2) ? s2W1 : fW1);
                const float* ev = (blk == 1) ? (wse + 52) : wse;
                float acc = 0.f;
                #pragma unroll 10
                for (int k = 0; k < NRBF_; k++) acc += W[k*HH + h] * ev[k];
                S.T[r*512 + cc] = acc;
            }
        }
    }

    float wv[4];
    #pragma unroll
    for (int q = 0; q < 4; q++)
        wv[q] = hf ? s2W2[tx*4 + q] : s1W2[tx*4 + q];
    const float b2 = hf ? s2b2[0] : s1b2[0];
    const float nv = 32.f - ((g == 7) ? 1.f : 0.f);

    for (int bi = blockIdx.x; bi < BN*NPT; bi += gridDim.x) {
        const int b = bi >> 8;
        const int i = bi & 255;
        const float* st = state + b*STRIDE_B;
        __syncthreads();   // covers table build on first iter; per-bi smem reuse after
        for (int e = tid; e < NPT*3; e += NT) S.xs[e] = st[e];
        if (tid < FF) S.feats_s[tid] = st[NPT*3 + i*FF + tid];
        __syncthreads();

        if (ty == 0) {  // softmax(feats_i)
            float v = S.feats_s[tx];
            float m = v;
            #pragma unroll
            for (int o = 16; o; o >>= 1) m = fmaxf(m, __shfl_xor_sync(0xffffffffu, m, o));
            float e = __expf(v - m);
            float s = e;
            #pragma unroll
            for (int o = 16; o; o >>= 1) s += __shfl_xor_sync(0xffffffffu, s, o);
            S.smax[tx] = e / s;
        }
        __syncthreads();

        // cvec from global weights (L2-hot)
        if (tid < 3*HH) {
            int net = tid >> 7, h = tid & 127;
            float c;
            if (net == 0) {
                c = s1b1[h];
                #pragma unroll 8
                for (int f = 0; f < FF; f++)
                    c += S.feats_s[f] * (s1W1[(NRBF_+f)*HH + h] + s1W1[(NRBF_+FF+f)*HH + h]);
            } else if (net == 1) {
                c = s2b1[h];
                #pragma unroll 8
                for (int f = 0; f < FF; f++)
                    c += S.feats_s[f] * (s2W1[(NRBF_+f)*HH + h] + s2W1[(NRBF_+FF+f)*HH + h]);
            } else {
                c = fb1[h];
                #pragma unroll 8
                for (int f = 0; f < FF; f++)
                    c += S.smax[f] * fW1[(NRBF_+f)*HH + h];
            }
            S.cvec[net][h] = c;
        }
        __syncthreads();

        float cA[4], cB[4];
        #pragma unroll
        for (int q = 0; q < 4; q++) {
            cA[q] = hf ? S.cvec[1][tx*4 + q] : S.cvec[0][tx*4 + q];
            cB[q] = hf ? S.cvec[2][tx*4 + q] : 0.f;
        }
        const float xi0 = S.xs[i*3+0], xi1 = S.xs[i*3+1], xi2 = S.xs[i*3+2];

        float a0=0.f, a1=0.f, a2=0.f, at=0.f;
        float rs0=0.f, rs1=0.f, rs2=0.f;
        float accf0=0.f, accf1=0.f, accf2=0.f, accf3=0.f;

        for (int tile = 0; tile < 4; tile++) {
            NB(g+1);
            if (hf == 0 && tx < 8) {
                int lp = g*8 + tx;
                int gp = tile*64 + lp;
                float r0 = 0.f, r1 = 0.f, r2 = 0.f;
                if (gp < NM1) {
                    int j = (gp < i) ? gp : gp + 1;
                    r0 = xi0 - S.xs[j*3+0];
                    r1 = xi1 - S.xs[j*3+1];
                    r2 = xi2 - S.xs[j*3+2];
                }
                float d2 = r0*r0 + r1*r1 + r2*r2 + EPSV;
                float ri = rsqrtf(d2);
                float d  = d2 * ri;
                S.pd[lp]  = d;
                S.pdi[lp] = ri;
                S.pr[lp*3+0] = r0; S.pr[lp*3+1] = r1; S.pr[lp*3+2] = r2;
                // Lagrange cubic weights at nodes idx-1..idx+2 (local u in [0,1))
                float s = d * INVH;
                int idx = (int)s;
                if (idx > IDXMAX) idx = IDXMAX;
                float u = s - (float)idx;
                float um1 = u - 1.f, up1 = u + 1.f, um2 = u - 2.f;
                S.pidx[lp] = idx;
                S.pw[lp][0] = pack2(-u*um1*um2*(1.f/6.f));
                S.pw[lp][1] = pack2( up1*um1*um2*0.5f);
                S.pw[lp][2] = pack2(-up1*u*um2*0.5f);
                S.pw[lp][3] = pack2( up1*u*um1*(1.f/6.f));
            }
            NB(g+1);

            // Interp "GEMM": 8 pairs x 256 cols (this half) via 4-tap cubic
            ull acc0[8][2], acc1[8][2];
            #pragma unroll
            for (int p = 0; p < 8; p++) {
                acc0[p][0]=0ull; acc0[p][1]=0ull;
                acc1[p][0]=0ull; acc1[p][1]=0ull;
            }
            const ull* Tu = reinterpret_cast<const ull*>(S.T) + hf*128 + tx*2;
            #pragma unroll
            for (int p = 0; p < 8; p++) {
                int lp = g*8 + p;
                const ull* Trow = Tu + S.pidx[lp]*256;
                ull w0 = S.pw[lp][0], w1 = S.pw[lp][1], w2 = S.pw[lp][2], w3 = S.pw[lp][3];
                ulonglong2 ta0 = *reinterpret_cast<const ulonglong2*>(Trow);
                ulonglong2 tb0 = *reinterpret_cast<const ulonglong2*>(Trow + 64);
                ulonglong2 ta1 = *reinterpret_cast<const ulonglong2*>(Trow + 256);
                ulonglong2 tb1 = *reinterpret_cast<const ulonglong2*>(Trow + 256 + 64);
                ffma2(acc0[p][0], ta0.x, w0); ffma2(acc0[p][1], ta0.y, w0);
                ffma2(acc1[p][0], tb0.x, w0); ffma2(acc1[p][1], tb0.y, w0);
                ffma2(acc0[p][0], ta1.x, w1); ffma2(acc0[p][1], ta1.y, w1);
                ffma2(acc1[p][0], tb1.x, w1); ffma2(acc1[p][1], tb1.y, w1);
                ulonglong2 ta2 = *reinterpret_cast<const ulonglong2*>(Trow + 512);
                ulonglong2 tb2 = *reinterpret_cast<const ulonglong2*>(Trow + 512 + 64);
                ulonglong2 ta3 = *reinterpret_cast<const ulonglong2*>(Trow + 768);
                ulonglong2 tb3 = *reinterpret_cast<const ulonglong2*>(Trow + 768 + 64);
                ffma2(acc0[p][0], ta2.x, w2); ffma2(acc0[p][1], ta2.y, w2);
                ffma2(acc1[p][0], tb2.x, w2); ffma2(acc1[p][1], tb2.y, w2);
                ffma2(acc0[p][0], ta3.x, w3); ffma2(acc0[p][1], ta3.y, w3);
                ffma2(acc1[p][0], tb3.x, w3); ffma2(acc1[p][1], tb3.y, w3);
            }

            // Epilogue: in-lane accumulation
            #pragma unroll
            for (int p = 0; p < 8; p++) {
                int lp = g*8 + p;
                int gp = tile*64 + lp;
                float d  = S.pd[lp];
                float ri = S.pdi[lp];
                float r0 = S.pr[lp*3+0], r1 = S.pr[lp*3+1], r2 = S.pr[lp*3+2];
                bool valid = (gp < NM1);
                if (hf == 0) {
                    float sc = 0.f, gc = 0.f;
                    #pragma unroll
                    for (int u = 0; u < 2; u++) {
                        float2 vA = unpack2(acc0[p][u]);
                        float2 vB = unpack2(acc1[p][u]);
                        #pragma unroll
                        for (int sub = 0; sub < 2; sub++) {
                            int q = u*2 + sub;
                            float phi1 = sub ? vA.y : vA.x;
                            float tG   = sub ? vB.y : vB.x;   // ds1pre/dd (tabulated)
                            float pre1 = phi1 + cA[q];
                            float sig  = __fdividef(1.f, 1.f + __expf(-pre1));
                            sc += pre1 * sig * wv[q];
                            float dsil = sig * (1.f + pre1 * (1.f - sig));
                            gc += wv[q] * dsil * tG;
                        }
                    }
                    if (valid) {
                        a0 += r0*sc; a1 += r1*sc; a2 += r2*sc;
                        float r2d = (d*d - EPSV) * ri;          // |r|^2 / d
                        at += r2d * gc + 3.f * sc;
                        rs0 += r0; rs1 += r1; rs2 += r2;
                    }
                } else {
                    float sc = 0.f;
                    float afq[4];
                    #pragma unroll
                    for (int u = 0; u < 2; u++) {
                        float2 vA = unpack2(acc0[p][u]);
                        float2 vB = unpack2(acc1[p][u]);
                        #pragma unroll
                        for (int sub = 0; sub < 2; sub++) {
                            int q = u*2 + sub;
                            float phi2 = sub ? vA.y : vA.x;
                            float phif = sub ? vB.y : vB.x;
                            float pre2 = phi2 + cA[q];
                            float sig2 = __fdividef(1.f, 1.f + __expf(-pre2));
                            sc += pre2 * sig2 * wv[q];
                            float pref = phif + cB[q];
                            float sigf = __fdividef(1.f, 1.f + __expf(-pref));
                            afq[q] = pref * sigf;
                        }
                    }
                    if (valid) {
                        a0 += r0*sc; a1 += r1*sc; a2 += r2*sc;
                        accf0 += afq[0]; accf1 += afq[1]; accf2 += afq[2]; accf3 += afq[3];
                        rs0 += r0; rs1 += r1; rs2 += r2;
                    }
                }
            }
        } // tiles

        #pragma unroll
        for (int o = 16; o; o >>= 1) {
            a0 += __shfl_xor_sync(0xffffffffu, a0, o);
            a1 += __shfl_xor_sync(0xffffffffu, a1, o);
            a2 += __shfl_xor_sync(0xffffffffu, a2, o);
            at += __shfl_xor_sync(0xffffffffu, at, o);
        }
        float c0 = a0 + b2*rs0;
        float c1 = a1 + b2*rs1;
        float c2 = a2 + b2*rs2;
        float ct = at + 3.f*b2*nv;

        if (hf == 1) {
            S.accst[g][tx*4+0] = accf0;
            S.accst[g][tx*4+1] = accf1;
            S.accst[g][tx*4+2] = accf2;
            S.accst[g][tx*4+3] = accf3;
        }
        if (tx == 0) {
            if (hf == 0) {
                S.wpart[ty][0] = c0; S.wpart[ty][1] = c1; S.wpart[ty][2] = c2;
                S.wpart[ty][3] = 0.f; S.wpart[ty][4] = 0.f; S.wpart[ty][5] = 0.f;
                S.wpart[ty][6] = ct;
            } else {
                S.wpart[ty][0] = 0.f; S.wpart[ty][1] = 0.f; S.wpart[ty][2] = 0.f;
                S.wpart[ty][3] = c0; S.wpart[ty][4] = c1; S.wpart[ty][5] = c2;
                S.wpart[ty][6] = 0.f;
            }
        }
        __syncthreads();
        if (tid < HH) {
            float t = 0.f;
            #pragma unroll
            for (int w = 0; w < 8; w++) t += S.accst[w][tid];
            S.accst[0][tid] = t;
        }
        __syncthreads();
        if (tid < FF) {
            float s = 0.f;
            #pragma unroll 16
            for (int h = 0; h < HH; h++) s += S.accst[0][h] * fW2[h*FF + tid];
            out[b*STRIDE_B + NPT*3 + i*FF + tid] = fb2[tid] + s * (1.f/255.f);
        }
        if (tid == 0) {
            float v0=0,v1=0,v2=0,w0=0,w1=0,w2=0,tr=0;
            #pragma unroll
            for (int w = 0; w < NW; w++) {
                v0 += S.wpart[w][0]; v1 += S.wpart[w][1]; v2 += S.wpart[w][2];
                w0 += S.wpart[w][3]; w1 += S.wpart[w][4]; w2 += S.wpart[w][5];
                tr += S.wpart[w][6];
            }
            const float inv = 1.f/255.f;
            v0 *= inv; v1 *= inv; v2 *= inv;
            w0 *= inv; w1 *= inv; w2 *= inv;
            float fx = v0 + (w1*v2 - w2*v1);
            float fy = v1 + (w2*v0 - w0*v2);
            float fz = v2 + (w0*v1 - w1*v0);
            g_vxf[bi*3+0] = fx; g_vxf[bi*3+1] = fy; g_vxf[bi*3+2] = fz;
            g_tr[bi] = tr * inv;
        }
    }

    // ---- Last-block finalization ----
    __syncthreads();
    if (tid == 0) {
        __threadfence();
        int v = atomicAdd(&g_done, 1);
        S.lastflag = (v == (int)gridDim.x - 1) ? 1.f : 0.f;
    }
    __syncthreads();
    if (S.lastflag != 0.f) {
        __threadfence();
        if (ty < BN) {
            float s0 = 0.f, s1 = 0.f, s2 = 0.f, st = 0.f;
            for (int ii = tx; ii < NPT; ii += 32) {
                int e = ty*NPT + ii;
                s0 += g_vxf[e*3+0]; s1 += g_vxf[e*3+1]; s2 += g_vxf[e*3+2];
                st += g_tr[e];
            }
            #pragma unroll
            for (int o = 16; o; o >>= 1) {
                s0 += __shfl_xor_sync(0xffffffffu, s0, o);
                s1 += __shfl_xor_sync(0xffffffffu, s1, o);
                s2 += __shfl_xor_sync(0xffffffffu, s2, o);
                st += __shfl_xor_sync(0xffffffffu, st, o);
            }
            if (tx == 0) {
                S.fin[ty*4+0] = s0 * (1.f/NPT);
                S.fin[ty*4+1] = s1 * (1.f/NPT);
                S.fin[ty*4+2] = s2 * (1.f/NPT);
                S.fin[ty*4+3] = st;
            }
        }
        __syncthreads();
        for (int e = tid; e < BN*NPT; e += NT) {
            int bb = e >> 8, ii = e & 255;
            float m0 = S.fin[bb*4+0], m1 = S.fin[bb*4+1], m2 = S.fin[bb*4+2];
            out[bb*STRIDE_B + ii*3+0] = g_vxf[e*3+0] - m0;
            out[bb*STRIDE_B + ii*3+1] = g_vxf[e*3+1] - m1;
            out[bb*STRIDE_B + ii*3+2] = g_vxf[e*3+2] - m2;
        }
        if (tid < BN) out[BN*STRIDE_B + tid] = S.fin[tid*4+3];
        if (tid == 0) g_done = 0;
    }
}

extern "C" void kernel_launch(void* const* d_in, const int* in_sizes, int n_in,
                              void* d_out, int out_size) {
    (void)in_sizes; (void)n_in; (void)out_size;
    const float* state = (const float*)d_in[1];
    const float* mus   = (const float*)d_in[2];
    const float* gamma = (const float*)d_in[3];
    const float* s1W1  = (const float*)d_in[4];
    const float* s1b1  = (const float*)d_in[5];
    const float* s1W2  = (const float*)d_in[6];
    const float* s1b2  = (const float*)d_in[7];
    const float* s2W1  = (const float*)d_in[8];
    const float* s2b1  = (const float*)d_in[9];
    const float* s2W2  = (const float*)d_in[10];
    const float* s2b2  = (const float*)d_in[11];
    const float* fW1   = (const float*)d_in[12];
    const float* fb1   = (const float*)d_in[13];
    const float* fW2   = (const float*)d_in[14];
    const float* fb2   = (const float*)d_in[15];
    float* out = (float*)d_out;

    const size_t smem = sizeof(SmemLayout);
    cudaFuncSetAttribute(k_main, cudaFuncAttributeMaxDynamicSharedMemorySize, (int)smem);

    k_main<<<NCTA, NT, smem>>>(state, mus, gamma,
                               s1W1, s1b1, s1W2, s1b2,
                               s2W1, s2b1, s2W2, s2b2,
                               fW1, fb1, fW2, fb2, out);
}